// round 4
// baseline (speedup 1.0000x reference)
#include <cuda_runtime.h>
#include <math_constants.h>

#define NROWS 8192
#define F     256
#define ALPHA 0.2f

// Scratch (allocation-free rule: __device__ globals)
__device__ __align__(16) float g_u1[F];
__device__ __align__(16) float g_u2[F];
__device__ __align__(16) float g_s1[NROWS];
__device__ __align__(16) float g_s2[NROWS];

// ---------------------------------------------------------------------------
// Kernel A: u1 = W @ a[:256], u2 = W @ a[256:]   (W is [F, F] row-major)
// one block, 256 threads; thread k computes u1[k], u2[k]
// ---------------------------------------------------------------------------
__global__ void compute_u_kernel(const float* __restrict__ W,
                                 const float* __restrict__ a) {
    __shared__ float sa[2 * F];
    int t = threadIdx.x;
    sa[t]     = a[t];
    sa[t + F] = a[t + F];
    __syncthreads();

    const float* wr = W + t * F;
    float u1 = 0.f, u2 = 0.f;
#pragma unroll 8
    for (int m = 0; m < F; m++) {
        float w = wr[m];
        u1 = fmaf(w, sa[m], u1);
        u2 = fmaf(w, sa[F + m], u2);
    }
    g_u1[t] = u1;
    g_u2[t] = u2;
}

// ---------------------------------------------------------------------------
// Kernel B: s1[i] = src[i,:]·u1, s2[i] = src[i,:]·u2
// one warp per row; blockDim 256 -> 8 rows/block; grid NROWS/8
// ---------------------------------------------------------------------------
__global__ void __launch_bounds__(256) compute_s_kernel(const float* __restrict__ src) {
    int gwarp = (blockIdx.x * blockDim.x + threadIdx.x) >> 5;  // row
    int lane  = threadIdx.x & 31;

    const float4* row = reinterpret_cast<const float4*>(src + (size_t)gwarp * F);
    const float4* u1v = reinterpret_cast<const float4*>(g_u1);
    const float4* u2v = reinterpret_cast<const float4*>(g_u2);

    float s1 = 0.f, s2 = 0.f;
#pragma unroll
    for (int i = 0; i < 2; i++) {
        int idx = lane + i * 32;           // 64 float4 per row
        float4 x = row[idx];
        float4 p = u1v[idx];
        float4 q = u2v[idx];
        s1 += x.x * p.x + x.y * p.y + x.z * p.z + x.w * p.w;
        s2 += x.x * q.x + x.y * q.y + x.z * q.z + x.w * q.w;
    }
#pragma unroll
    for (int o = 16; o > 0; o >>= 1) {
        s1 += __shfl_xor_sync(0xffffffffu, s1, o);
        s2 += __shfl_xor_sync(0xffffffffu, s2, o);
    }
    if (lane == 0) {
        g_s1[gwarp] = s1;
        g_s2[gwarp] = s2;
    }
}

// ---------------------------------------------------------------------------
// Kernel C: fused e / leakyrelu / +bias / row-softmax, single pass over bias.
// One CTA per row, 512 threads, 4 float4 (16 floats) per thread in registers.
// Explicit front-batched load phase (MLP_p1 = 8 independent loads/thread),
// then compute. Two-level online softmax: per-warp (max, sum) via shuffles,
// ONE block barrier, every thread combines the 16 warp pairs redundantly.
// bias read + out write use streaming (evict-first) hints.
// ---------------------------------------------------------------------------
__device__ __forceinline__ float lrelu(float x) {
    return x > 0.f ? x : ALPHA * x;
}

#define CTHREADS 512
#define NWARPS   (CTHREADS / 32)
#define VPT      4    // float4 per thread; CTHREADS*VPT*4 == NROWS

__global__ void __launch_bounds__(CTHREADS) softmax_row_kernel(const float* __restrict__ bias,
                                                               float* __restrict__ out) {
    const int row  = blockIdx.x;
    const int t    = threadIdx.x;
    const int lane = t & 31;
    const int wid  = t >> 5;          // 0..15

    const float s1 = g_s1[row];
    const float4* brow = reinterpret_cast<const float4*>(bias + (size_t)row * NROWS);
    float4*       orow = reinterpret_cast<float4*>(out + (size_t)row * NROWS);
    const float4* s2v  = reinterpret_cast<const float4*>(g_s2);

    // ---- load phase: 8 independent loads issued back-to-back ----
    float4 b[VPT], s[VPT];
#pragma unroll
    for (int i = 0; i < VPT; i++)
        b[i] = __ldcs(&brow[t + i * CTHREADS]);   // streaming, evict-first
#pragma unroll
    for (int i = 0; i < VPT; i++)
        s[i] = s2v[t + i * CTHREADS];             // L2-resident broadcast

    // ---- compute phase: e = lrelu(s1 + s2) + bias, warp-local max ----
    float4 e[VPT];
    float mx = -CUDART_INF_F;
#pragma unroll
    for (int i = 0; i < VPT; i++) {
        float4 v;
        v.x = lrelu(s1 + s[i].x) + b[i].x;
        v.y = lrelu(s1 + s[i].y) + b[i].y;
        v.z = lrelu(s1 + s[i].z) + b[i].z;
        v.w = lrelu(s1 + s[i].w) + b[i].w;
        e[i] = v;
        mx = fmaxf(mx, fmaxf(fmaxf(v.x, v.y), fmaxf(v.z, v.w)));
    }
#pragma unroll
    for (int o = 16; o > 0; o >>= 1)
        mx = fmaxf(mx, __shfl_xor_sync(0xffffffffu, mx, o));
    // mx is now the warp max (uniform within warp)

    // ---- exp relative to warp max, warp-local sum ----
    float sum = 0.f;
#pragma unroll
    for (int i = 0; i < VPT; i++) {
        e[i].x = __expf(e[i].x - mx);
        e[i].y = __expf(e[i].y - mx);
        e[i].z = __expf(e[i].z - mx);
        e[i].w = __expf(e[i].w - mx);
        sum += (e[i].x + e[i].y) + (e[i].z + e[i].w);
    }
#pragma unroll
    for (int o = 16; o > 0; o >>= 1)
        sum += __shfl_xor_sync(0xffffffffu, sum, o);

    // ---- combine 16 warp (max, sum) pairs: single barrier ----
    __shared__ float2 wred[NWARPS];
    if (lane == 0) wred[wid] = make_float2(mx, sum);
    __syncthreads();

    float M = -CUDART_INF_F;
#pragma unroll
    for (int w = 0; w < NWARPS; w++)
        M = fmaxf(M, wred[w].x);
    float S = 0.f;
#pragma unroll
    for (int w = 0; w < NWARPS; w++)
        S += wred[w].y * __expf(wred[w].x - M);

    // elements hold exp(v - mx_warp); final weight is
    // exp(v - M)/S = exp(v - mx_warp) * exp(mx_warp - M) / S
    const float corr = __expf(mx - M) * __frcp_rn(S);

    // ---- scaled streaming store ----
#pragma unroll
    for (int i = 0; i < VPT; i++) {
        float4 v = e[i];
        v.x *= corr; v.y *= corr; v.z *= corr; v.w *= corr;
        __stcs(&orow[t + i * CTHREADS], v);       // streaming, evict-first
    }
}

// ---------------------------------------------------------------------------
extern "C" void kernel_launch(void* const* d_in, const int* in_sizes, int n_in,
                              void* d_out, int out_size) {
    // Resolve inputs by unique element counts (robust to metadata ordering):
    //   src  : 8192*256   = 2097152
    //   bias : 8192*8192  = 67108864
    //   W    : 256*256    = 65536
    //   a    : 512*1      = 512
    const float* src  = nullptr;
    const float* bias = nullptr;
    const float* W    = nullptr;
    const float* a    = nullptr;
    for (int i = 0; i < n_in; i++) {
        switch (in_sizes[i]) {
            case 2097152:  src  = (const float*)d_in[i]; break;
            case 67108864: bias = (const float*)d_in[i]; break;
            case 65536:    W    = (const float*)d_in[i]; break;
            case 512:      a    = (const float*)d_in[i]; break;
        }
    }
    float* out = (float*)d_out;  // [8192, 8192]

    compute_u_kernel<<<1, 256>>>(W, a);
    compute_s_kernel<<<NROWS / 8, 256>>>(src);
    softmax_row_kernel<<<NROWS, CTHREADS>>>(bias, out);
}

// round 13
// speedup vs baseline: 1.3336x; 1.3336x over previous
#include <cuda_runtime.h>
#include <math_constants.h>

#define NROWS 8192
#define F     256
#define ALPHA 0.2f

// Scratch (allocation-free rule: __device__ globals)
__device__ __align__(16) float g_u1[F];
__device__ __align__(16) float g_u2[F];
__device__ __align__(16) float g_s1[NROWS];
__device__ __align__(16) float g_s2[NROWS];

// ---------------------------------------------------------------------------
// Kernel A: u1[r] = W[r,:]·a[:256], u2[r] = W[r,:]·a[256:]
// WARP-PER-ROW (coalesced float4): was thread-per-row with 1024B-strided
// warp access -> nL=32 lines per LDG -> 37.6us measured. Now each warp
// streams its 1KB row contiguously. grid=32 blocks x 256 thr = 256 warps.
// Predicted <3us (launch-overhead bound).
// ---------------------------------------------------------------------------
__global__ void __launch_bounds__(256) compute_u_kernel(const float* __restrict__ W,
                                                        const float* __restrict__ a) {
    const int gwarp = (blockIdx.x * blockDim.x + threadIdx.x) >> 5;  // row 0..255
    const int lane  = threadIdx.x & 31;

    const float4* row = reinterpret_cast<const float4*>(W + (size_t)gwarp * F);
    const float4* a1v = reinterpret_cast<const float4*>(a);        // a[0:256]
    const float4* a2v = reinterpret_cast<const float4*>(a + F);    // a[256:512]

    float u1 = 0.f, u2 = 0.f;
#pragma unroll
    for (int i = 0; i < 2; i++) {
        int idx = lane + i * 32;            // 64 float4 per row
        float4 w = row[idx];
        float4 p = __ldg(&a1v[idx]);
        float4 q = __ldg(&a2v[idx]);
        u1 += w.x * p.x + w.y * p.y + w.z * p.z + w.w * p.w;
        u2 += w.x * q.x + w.y * q.y + w.z * q.z + w.w * q.w;
    }
#pragma unroll
    for (int o = 16; o > 0; o >>= 1) {
        u1 += __shfl_xor_sync(0xffffffffu, u1, o);
        u2 += __shfl_xor_sync(0xffffffffu, u2, o);
    }
    if (lane == 0) {
        g_u1[gwarp] = u1;
        g_u2[gwarp] = u2;
    }
}

// ---------------------------------------------------------------------------
// Kernel B: s1[i] = src[i,:]·u1, s2[i] = src[i,:]·u2
// one warp per row; blockDim 256 -> 8 rows/block; grid NROWS/8
// ---------------------------------------------------------------------------
__global__ void __launch_bounds__(256) compute_s_kernel(const float* __restrict__ src) {
    int gwarp = (blockIdx.x * blockDim.x + threadIdx.x) >> 5;  // row
    int lane  = threadIdx.x & 31;

    const float4* row = reinterpret_cast<const float4*>(src + (size_t)gwarp * F);
    const float4* u1v = reinterpret_cast<const float4*>(g_u1);
    const float4* u2v = reinterpret_cast<const float4*>(g_u2);

    float s1 = 0.f, s2 = 0.f;
#pragma unroll
    for (int i = 0; i < 2; i++) {
        int idx = lane + i * 32;           // 64 float4 per row
        float4 x = row[idx];
        float4 p = u1v[idx];
        float4 q = u2v[idx];
        s1 += x.x * p.x + x.y * p.y + x.z * p.z + x.w * p.w;
        s2 += x.x * q.x + x.y * q.y + x.z * q.z + x.w * q.w;
    }
#pragma unroll
    for (int o = 16; o > 0; o >>= 1) {
        s1 += __shfl_xor_sync(0xffffffffu, s1, o);
        s2 += __shfl_xor_sync(0xffffffffu, s2, o);
    }
    if (lane == 0) {
        g_s1[gwarp] = s1;
        g_s2[gwarp] = s2;
    }
}

// ---------------------------------------------------------------------------
// Kernel C: fused e / leakyrelu / +bias / row-softmax, single pass over bias.
// One CTA per row, 512 threads, 4 float4 (16 floats) per thread in registers.
// Explicit front-batched load phase (MLP_p1 = 8 independent loads/thread),
// then compute. Two-level online softmax: per-warp (max, sum) via shuffles,
// ONE block barrier, every thread combines the 16 warp pairs redundantly.
// bias read + out write use streaming (evict-first) hints.
// ---------------------------------------------------------------------------
__device__ __forceinline__ float lrelu(float x) {
    return x > 0.f ? x : ALPHA * x;
}

#define CTHREADS 512
#define NWARPS   (CTHREADS / 32)
#define VPT      4    // float4 per thread; CTHREADS*VPT*4 == NROWS

__global__ void __launch_bounds__(CTHREADS) softmax_row_kernel(const float* __restrict__ bias,
                                                               float* __restrict__ out) {
    const int row  = blockIdx.x;
    const int t    = threadIdx.x;
    const int lane = t & 31;
    const int wid  = t >> 5;          // 0..15

    const float s1 = g_s1[row];
    const float4* brow = reinterpret_cast<const float4*>(bias + (size_t)row * NROWS);
    float4*       orow = reinterpret_cast<float4*>(out + (size_t)row * NROWS);
    const float4* s2v  = reinterpret_cast<const float4*>(g_s2);

    // ---- load phase: 8 independent loads issued back-to-back ----
    float4 b[VPT], s[VPT];
#pragma unroll
    for (int i = 0; i < VPT; i++)
        b[i] = __ldcs(&brow[t + i * CTHREADS]);   // streaming, evict-first
#pragma unroll
    for (int i = 0; i < VPT; i++)
        s[i] = s2v[t + i * CTHREADS];             // L2-resident broadcast

    // ---- compute phase: e = lrelu(s1 + s2) + bias, warp-local max ----
    float4 e[VPT];
    float mx = -CUDART_INF_F;
#pragma unroll
    for (int i = 0; i < VPT; i++) {
        float4 v;
        v.x = lrelu(s1 + s[i].x) + b[i].x;
        v.y = lrelu(s1 + s[i].y) + b[i].y;
        v.z = lrelu(s1 + s[i].z) + b[i].z;
        v.w = lrelu(s1 + s[i].w) + b[i].w;
        e[i] = v;
        mx = fmaxf(mx, fmaxf(fmaxf(v.x, v.y), fmaxf(v.z, v.w)));
    }
#pragma unroll
    for (int o = 16; o > 0; o >>= 1)
        mx = fmaxf(mx, __shfl_xor_sync(0xffffffffu, mx, o));
    // mx is now the warp max (uniform within warp)

    // ---- exp relative to warp max, warp-local sum ----
    float sum = 0.f;
#pragma unroll
    for (int i = 0; i < VPT; i++) {
        e[i].x = __expf(e[i].x - mx);
        e[i].y = __expf(e[i].y - mx);
        e[i].z = __expf(e[i].z - mx);
        e[i].w = __expf(e[i].w - mx);
        sum += (e[i].x + e[i].y) + (e[i].z + e[i].w);
    }
#pragma unroll
    for (int o = 16; o > 0; o >>= 1)
        sum += __shfl_xor_sync(0xffffffffu, sum, o);

    // ---- combine 16 warp (max, sum) pairs: single barrier ----
    __shared__ float2 wred[NWARPS];
    if (lane == 0) wred[wid] = make_float2(mx, sum);
    __syncthreads();

    float M = -CUDART_INF_F;
#pragma unroll
    for (int w = 0; w < NWARPS; w++)
        M = fmaxf(M, wred[w].x);
    float S = 0.f;
#pragma unroll
    for (int w = 0; w < NWARPS; w++)
        S += wred[w].y * __expf(wred[w].x - M);

    // elements hold exp(v - mx_warp); final weight is
    // exp(v - M)/S = exp(v - mx_warp) * exp(mx_warp - M) / S
    const float corr = __expf(mx - M) * __frcp_rn(S);

    // ---- scaled streaming store ----
#pragma unroll
    for (int i = 0; i < VPT; i++) {
        float4 v = e[i];
        v.x *= corr; v.y *= corr; v.z *= corr; v.w *= corr;
        __stcs(&orow[t + i * CTHREADS], v);       // streaming, evict-first
    }
}

// ---------------------------------------------------------------------------
extern "C" void kernel_launch(void* const* d_in, const int* in_sizes, int n_in,
                              void* d_out, int out_size) {
    // Resolve inputs by unique element counts (robust to metadata ordering):
    //   src  : 8192*256   = 2097152
    //   bias : 8192*8192  = 67108864
    //   W    : 256*256    = 65536
    //   a    : 512*1      = 512
    const float* src  = nullptr;
    const float* bias = nullptr;
    const float* W    = nullptr;
    const float* a    = nullptr;
    for (int i = 0; i < n_in; i++) {
        switch (in_sizes[i]) {
            case 2097152:  src  = (const float*)d_in[i]; break;
            case 67108864: bias = (const float*)d_in[i]; break;
            case 65536:    W    = (const float*)d_in[i]; break;
            case 512:      a    = (const float*)d_in[i]; break;
        }
    }
    float* out = (float*)d_out;  // [8192, 8192]

    compute_u_kernel<<<F / 8, 256>>>(W, a);       // 32 blocks, warp-per-row
    compute_s_kernel<<<NROWS / 8, 256>>>(src);
    softmax_row_kernel<<<NROWS, CTHREADS>>>(bias, out);
}